// round 14
// baseline (speedup 1.0000x reference)
#include <cuda_runtime.h>
#include <math.h>

#define BB 2
#define CC 128
#define TT 512
#define FF 64
#define HH 32
#define DD 32

typedef unsigned long long u64;

// -------- f32x2 packed-FMA helpers (sm_103a) --------
__device__ __forceinline__ u64 pack2(float lo, float hi) {
    u64 r; asm("mov.b64 %0,{%1,%2};" : "=l"(r) : "f"(lo), "f"(hi)); return r;
}
__device__ __forceinline__ void unpack2(u64 v, float& a, float& b) {
    asm("mov.b64 {%0,%1},%2;" : "=f"(a), "=f"(b) : "l"(v));
}
__device__ __forceinline__ u64 fma2(u64 a, u64 b, u64 c) {
    u64 d; asm("fma.rn.f32x2 %0,%1,%2,%3;" : "=l"(d) : "l"(a), "l"(b), "l"(c)); return d;
}

// -------- scratch (device globals: allocation-free) --------
__device__ float g_xm1[BB*HH*TT*FF];   // (b,h,t,f)
__device__ float g_xf1[BB*HH*TT*FF];   // (b,h,t,f)
__device__ float g_corr[BB*HH*TT*DD];  // (b,h,t,d)
// packed dup softmax weights, 8t-group layout:
// g_swq[(b*8+tile)*2496 + tg*312 + rl*8 + ii], tg in [0,8), rl in [0,39), ii in [0,8)
__device__ u64   g_swq[BB*8*2496];

// tiny no-op kernel: shifts launch index so ncu's fixed capture slot (4th
// launch) lands on proj_kernel(which=1) for diagnostics.
__global__ void nop_kernel() {}

// ============================================================
// K1 (one projection per launch): out[b,h,t,f] = sum_c x*w + bias
// (R11 inner config: 256 threads, 128 blocks, 2 t-rows, full 32 h)
// ============================================================
__global__ void __launch_bounds__(256) proj_kernel(
    const float* __restrict__ x,
    const float* __restrict__ w,
    const float* __restrict__ bias,
    int which)
{
    __shared__ __align__(16) float ws[CC*HH];   // [c][h]
    __shared__ float bs[HH];
    float* outg = which ? g_xf1 : g_xm1;

    int tid = threadIdx.x;
    for (int i = tid; i < CC*HH; i += 256) ws[i] = w[i];
    if (tid < HH) bs[tid] = bias[tid];
    __syncthreads();

    int f  = tid & 63;
    int tp = tid >> 6;                       // 0..3
    int bx = blockIdx.x;
    int b  = bx >> 6;
    int t  = (((bx & 63) << 2) + tp) << 1;   // even t; thread does t and t+1

    u64 acc0[16], acc1[16];
#pragma unroll
    for (int i = 0; i < 16; i++) { acc0[i] = 0ull; acc1[i] = 0ull; }

    const float* xp = x + ((size_t)b*CC*TT + t)*FF + f;

#pragma unroll 1
    for (int c0 = 0; c0 < CC; c0 += 8) {
        float va[8], vb[8];
#pragma unroll
        for (int j = 0; j < 8; j++) {
            const float* p = xp + (size_t)(c0+j)*TT*FF;
            va[j] = p[0];
            vb[j] = p[FF];
        }
#pragma unroll
        for (int j = 0; j < 8; j++) {
            u64 pa = pack2(va[j], va[j]);
            u64 pb = pack2(vb[j], vb[j]);
            const ulonglong2* wq = (const ulonglong2*)(ws + (c0+j)*HH);
#pragma unroll
            for (int q = 0; q < 8; q++) {
                ulonglong2 wv = wq[q];
                acc0[2*q]   = fma2(pa, wv.x, acc0[2*q]);
                acc0[2*q+1] = fma2(pa, wv.y, acc0[2*q+1]);
                acc1[2*q]   = fma2(pb, wv.x, acc1[2*q]);
                acc1[2*q+1] = fma2(pb, wv.y, acc1[2*q+1]);
            }
        }
    }

#pragma unroll
    for (int q = 0; q < 16; q++) {
        float a0, a1, c0v, c1v;
        unpack2(acc0[q], a0, a1);
        unpack2(acc1[q], c0v, c1v);
        int h0 = 2*q, h1 = 2*q+1;
        float* o0 = outg + ((size_t)(b*HH+h0)*TT + t)*FF + f;
        float* o1 = outg + ((size_t)(b*HH+h1)*TT + t)*FF + f;
        o0[0]  = a0  + bs[h0];
        o0[FF] = c0v + bs[h0];
        o1[0]  = a1  + bs[h1];
        o1[FF] = c1v + bs[h1];
    }
}

// ============================================================
// K2: banded correlation — exact R11 version (K2S=70, LDS.64)
// ============================================================
#define K2T 64
#define K2S 70
__global__ void __launch_bounds__(256) corr_kernel()
{
    __shared__ float sm[K2T*K2S];
    __shared__ float sf[(K2T+31)*K2S];

    int b = blockIdx.z, h = blockIdx.y, t0 = blockIdx.x * K2T;
    int tid = threadIdx.x;   // 256

    const float* xmp = g_xm1 + ((size_t)(b*HH+h)*TT)*FF;
    const float* xfp = g_xf1 + ((size_t)(b*HH+h)*TT)*FF;

    for (int i = tid; i < K2T*FF; i += 256) {
        int r = i >> 6, fc = i & 63;
        sm[r*K2S + fc] = xmp[(size_t)(t0+r)*FF + fc];
    }
    for (int i = tid; i < (K2T+31)*FF; i += 256) {
        int r = i >> 6, fc = i & 63;
        int tt = t0 + r - 31;
        sf[r*K2S + fc] = (tt >= 0) ? xfp[(size_t)tt*FF + fc] : 0.f;
    }
    __syncthreads();

    int tl0 = (tid >> 3) << 1;   // 0,2,...,62
    int d0  = (tid & 7)  << 2;   // 0,4,...,28

    u64 acc[2][4];
#pragma unroll
    for (int i = 0; i < 2; i++)
#pragma unroll
        for (int j = 0; j < 4; j++) acc[i][j] = 0ull;

#pragma unroll 4
    for (int fcp = 0; fcp < FF/2; fcp++) {
        u64 a[2], br[5];
#pragma unroll
        for (int i = 0; i < 2; i++)
            a[i] = *(const u64*)(sm + (tl0+i)*K2S + fcp*2);
#pragma unroll
        for (int k = 0; k < 5; k++)
            br[k] = *(const u64*)(sf + (tl0+d0+k)*K2S + fcp*2);
#pragma unroll
        for (int i = 0; i < 2; i++)
#pragma unroll
            for (int j = 0; j < 4; j++)
                acc[i][j] = fma2(a[i], br[i+j], acc[i][j]);
    }

#pragma unroll
    for (int i = 0; i < 2; i++) {
        float4 v; float x0, x1;
        unpack2(acc[i][0], x0, x1); v.x = x0 + x1;
        unpack2(acc[i][1], x0, x1); v.y = x0 + x1;
        unpack2(acc[i][2], x0, x1); v.z = x0 + x1;
        unpack2(acc[i][3], x0, x1); v.w = x0 + x1;
        *(float4*)(g_corr + (((size_t)(b*HH+h)*TT + (t0+tl0+i))*DD + d0)) = v;
    }
}

// ============================================================
// K3: conv + mask + softmax; scatters weights into 8t-group g_swq — R11
// ============================================================
__global__ void conv_softmax_kernel(const float* __restrict__ wc,
                                    const float* __restrict__ bc)
{
    __shared__ float sc[16][12*36];
    __shared__ float wcs[HH*15];
    int tid = threadIdx.x;  // 256
    int b = blockIdx.y, t0 = blockIdx.x * 8;

    for (int i = tid; i < HH*15; i += 256) wcs[i] = wc[i];

    int d  = tid & 31;
    int tl = tid >> 5;
    float acc = 0.f;

#pragma unroll 1
    for (int ph = 0; ph < 2; ph++) {
        __syncthreads();
        const float* cpb = g_corr + ((size_t)(b*HH + ph*16)*TT)*DD;
        for (int i = tid; i < 16*12*34; i += 256) {
            int h   = i / 408;
            int rem = i - h*408;
            int r   = rem / 34;
            int col = rem - r*34;
            int tt = t0 - 3 + r, dd = col - 1;
            float v = 0.f;
            if (tt >= 0 && tt < TT && dd >= 0 && dd < DD)
                v = cpb[(size_t)h*TT*DD + (size_t)tt*DD + dd];
            sc[h][r*36 + col] = v;
        }
        __syncthreads();
#pragma unroll 1
        for (int h = 0; h < 16; h++) {
            const float* s  = sc[h] + tl*36 + d;
            const float* wv = wcs + (ph*16 + h)*15;
#pragma unroll
            for (int kh = 0; kh < 5; kh++)
#pragma unroll
                for (int kw = 0; kw < 3; kw++)
                    acc = fmaf(s[kh*36 + kw], wv[kh*3 + kw], acc);
        }
    }

    acc += bc[0];
    int t = t0 + tl;
    if (t + d < DD - 1) acc = -1e13f;

    float m = acc;
#pragma unroll
    for (int o = 16; o; o >>= 1) m = fmaxf(m, __shfl_xor_sync(0xffffffffu, m, o));
    float e = expf(acc - m);
    float s = e;
#pragma unroll
    for (int o = 16; o; o >>= 1) s += __shfl_xor_sync(0xffffffffu, s, o);

    float wv = e / s;

    // scatter into 8t packed layout
    int tile = t >> 6;
    int tg   = (t >> 3) & 7;
    int ii   = t & 7;
    u64* base = g_swq + (size_t)(b*8 + tile)*2496 + tg*312;
    base[(d + ii)*8 + ii] = pack2(wv, wv);
    if (d < 7) {
        int rl = (d < ii) ? d : 32 + d;
        base[rl*8 + ii] = 0ull;
    }
}

// ============================================================
// K4: out[b,c,t,f] = sum_d w[b,t,d] * xf[b,c,t+d-31,f] — R11
// ============================================================
#define K4T 64
__global__ void __launch_bounds__(256) out_kernel(const float* __restrict__ xf,
                                                  float* __restrict__ out)
{
    __shared__ __align__(16) float sx[2][(K4T+31)*FF];  // 48640 B
    __shared__ __align__(16) u64 swq[2496];              // 19968 B

    int b = blockIdx.z, cpair = blockIdx.y, tile = blockIdx.x;
    int t0 = tile * K4T;
    int tid = threadIdx.x;  // 256

    {
        int base4 = (t0 - 31) * (FF/4);
#pragma unroll
        for (int cs = 0; cs < 2; cs++) {
            const float4* xp4 = (const float4*)(xf + ((size_t)(b*CC + cpair*2 + cs)*TT)*FF);
            float4* sx4 = (float4*)sx[cs];
#pragma unroll
            for (int k = 0; k < 6; k++) {
                int i = tid + k*256;
                if (i < (K4T+31)*(FF/4)) {
                    int src = base4 + i;
                    sx4[i] = (src >= 0) ? xp4[src]
                                        : make_float4(0.f, 0.f, 0.f, 0.f);
                }
            }
        }
    }
    {
        const uint4* src = (const uint4*)(g_swq + (size_t)(b*8 + tile)*2496);
        uint4* dst = (uint4*)swq;
#pragma unroll
        for (int k = 0; k < 5; k++) {
            int i = tid + k*256;
            if (i < 1248) dst[i] = src[i];
        }
    }
    __syncthreads();

    int cs = tid >> 7;
    int r  = tid & 127;
    int fq = r & 15;
    int tg = r >> 4;
    int tb = tg << 3;

    u64 acc[8][2];
#pragma unroll
    for (int i = 0; i < 8; i++) { acc[i][0] = 0ull; acc[i][1] = 0ull; }

    const float* xrow = sx[cs] + tb*FF + fq*4;
    const ulonglong2* wq = (const ulonglong2*)(swq + (size_t)tg*312);

#pragma unroll 3
    for (int rl = 0; rl < 39; rl++) {
        ulonglong2 xv = *(const ulonglong2*)(xrow + rl*FF);
        ulonglong2 q0 = wq[rl*4];
        ulonglong2 q1 = wq[rl*4 + 1];
        ulonglong2 q2 = wq[rl*4 + 2];
        ulonglong2 q3 = wq[rl*4 + 3];
        acc[0][0] = fma2(xv.x, q0.x, acc[0][0]);
        acc[0][1] = fma2(xv.y, q0.x, acc[0][1]);
        acc[1][0] = fma2(xv.x, q0.y, acc[1][0]);
        acc[1][1] = fma2(xv.y, q0.y, acc[1][1]);
        acc[2][0] = fma2(xv.x, q1.x, acc[2][0]);
        acc[2][1] = fma2(xv.y, q1.x, acc[2][1]);
        acc[3][0] = fma2(xv.x, q1.y, acc[3][0]);
        acc[3][1] = fma2(xv.y, q1.y, acc[3][1]);
        acc[4][0] = fma2(xv.x, q2.x, acc[4][0]);
        acc[4][1] = fma2(xv.y, q2.x, acc[4][1]);
        acc[5][0] = fma2(xv.x, q2.y, acc[5][0]);
        acc[5][1] = fma2(xv.y, q2.y, acc[5][1]);
        acc[6][0] = fma2(xv.x, q3.x, acc[6][0]);
        acc[6][1] = fma2(xv.y, q3.x, acc[6][1]);
        acc[7][0] = fma2(xv.x, q3.y, acc[7][0]);
        acc[7][1] = fma2(xv.y, q3.y, acc[7][1]);
    }

    float* op = out + ((size_t)(b*CC + cpair*2 + cs)*TT + (t0 + tb))*FF + fq*4;
#pragma unroll
    for (int i = 0; i < 8; i++) {
        float4 v;
        unpack2(acc[i][0], v.x, v.y);
        unpack2(acc[i][1], v.z, v.w);
        *(float4*)(op + (size_t)i*FF) = v;
    }
}

// ============================================================
extern "C" void kernel_launch(void* const* d_in, const int* in_sizes, int n_in,
                              void* d_out, int out_size)
{
    const float* xm = (const float*)d_in[0];
    const float* xf = (const float*)d_in[1];
    const float* w1 = (const float*)d_in[2];
    const float* b1 = (const float*)d_in[3];
    const float* w2 = (const float*)d_in[4];
    const float* b2 = (const float*)d_in[5];
    const float* wc = (const float*)d_in[6];
    const float* bc = (const float*)d_in[7];
    float* out = (float*)d_out;

    (void)in_sizes; (void)n_in; (void)out_size;

    // launches #1,#2: no-ops so the profiler's fixed capture slot (#4)
    // lands on the xf projection (half of K1).
    nop_kernel<<<1, 32>>>();
    nop_kernel<<<1, 32>>>();

    proj_kernel<<<128, 256>>>(xm, w1, b1, 0);   // #3
    proj_kernel<<<128, 256>>>(xf, w2, b2, 1);   // #4  <- profiled

    dim3 g2(TT/K2T, HH, BB);
    corr_kernel<<<g2, 256>>>();

    dim3 g3(TT/8, BB);
    conv_softmax_kernel<<<g3, 256>>>(wc, bc);

    dim3 g4(TT/K4T, CC/2, BB);
    out_kernel<<<g4, 256>>>(xf, out);
}

// round 15
// speedup vs baseline: 1.2166x; 1.2166x over previous
#include <cuda_runtime.h>
#include <math.h>

#define BB 2
#define CC 128
#define TT 512
#define FF 64
#define HH 32
#define DD 32

typedef unsigned long long u64;

// -------- f32x2 packed-FMA helpers (sm_103a) --------
__device__ __forceinline__ u64 pack2(float lo, float hi) {
    u64 r; asm("mov.b64 %0,{%1,%2};" : "=l"(r) : "f"(lo), "f"(hi)); return r;
}
__device__ __forceinline__ void unpack2(u64 v, float& a, float& b) {
    asm("mov.b64 {%0,%1},%2;" : "=f"(a), "=f"(b) : "l"(v));
}
__device__ __forceinline__ u64 fma2(u64 a, u64 b, u64 c) {
    u64 d; asm("fma.rn.f32x2 %0,%1,%2,%3;" : "=l"(d) : "l"(a), "l"(b), "l"(c)); return d;
}
__device__ __forceinline__ unsigned smem_u32(const void* p) {
    return (unsigned)__cvta_generic_to_shared(p);
}
__device__ __forceinline__ void cp16(unsigned dst, const void* src) {
    asm volatile("cp.async.cg.shared.global [%0], [%1], 16;" :: "r"(dst), "l"(src));
}

// -------- scratch (device globals: allocation-free) --------
__device__ float g_xm1[BB*HH*TT*FF];   // (b,h,t,f)
__device__ float g_xf1[BB*HH*TT*FF];   // (b,h,t,f)
__device__ float g_corr[BB*HH*TT*DD];  // (b,h,t,d)
// packed dup softmax weights, 8t-group layout:
// g_swq[(b*8+tile)*2496 + tg*312 + rl*8 + ii]
__device__ u64   g_swq[BB*8*2496];

// no-op kernels: shift ncu's fixed capture slot (4th launch) onto proj.
__global__ void nop_kernel() {}

// ============================================================
// K1 (fused both projections): out[b,h,t,f] = sum_c x[b,c,t,f]*w[c,h] + bias[h]
// cp.async 3-stage pipeline stages x c-chunks (8 c x 8 t x 64 f = 16KB)
// into smem; LDG latency fully hidden, inner FFMA2 loop unchanged.
// 256 threads, dim3(128,2); thread = (f, t-pair), 2 t-rows, 32 h accs.
// ============================================================
#define PCH 8    // c per chunk
#define PST 3    // pipeline stages
__global__ void __launch_bounds__(256) proj_kernel(
    const float* __restrict__ xm, const float* __restrict__ xf,
    const float* __restrict__ w1, const float* __restrict__ b1,
    const float* __restrict__ w2, const float* __restrict__ b2)
{
    __shared__ __align__(16) float ws[CC*HH];           // 16 KB
    __shared__ float bs[HH];
    __shared__ __align__(16) float sx[PST][PCH*8*FF];   // 48 KB

    int which = blockIdx.y;
    const float* x    = which ? xf : xm;
    const float* w    = which ? w2 : w1;
    const float* bias = which ? b2 : b1;
    float* outg = which ? g_xf1 : g_xm1;

    int tid = threadIdx.x;
    for (int i = tid; i < CC*HH; i += 256) ws[i] = w[i];
    if (tid < HH) bs[tid] = bias[tid];

    int f  = tid & 63;
    int tp = tid >> 6;              // 0..3
    int bx = blockIdx.x;
    int b  = bx >> 6;
    int t0 = (bx & 63) * 8;         // 8 t-rows per block

    const float* xbase = x + ((size_t)b*CC*TT + t0)*FF;

    // this thread's 4 load slots (fixed across chunks): q = tid + j*256
    // c = q>>7, r = q&127, t = r>>4, f4 = r&15
    // prologue: chunks 0..PST-1
#pragma unroll
    for (int s = 0; s < PST; s++) {
#pragma unroll
        for (int j = 0; j < 4; j++) {
            int q = tid + j*256;
            int c = q >> 7, r = q & 127;
            int tt = r >> 4, f4 = r & 15;
            cp16(smem_u32(&sx[s][q*4]),
                 xbase + (size_t)(s*PCH + c)*TT*FF + tt*FF + f4*4);
        }
        asm volatile("cp.async.commit_group;");
    }

    u64 acc0[16], acc1[16];
#pragma unroll
    for (int i = 0; i < 16; i++) { acc0[i] = 0ull; acc1[i] = 0ull; }

    int tl0 = tp*2, tl1 = tp*2 + 1;

#pragma unroll 1
    for (int k = 0; k < CC/PCH; k++) {
        asm volatile("cp.async.wait_group %0;" :: "n"(PST-1));
        __syncthreads();                 // chunk k visible to all (also covers ws on k=0)
        int st = k % PST;
        const float* sxp = sx[st];
        int cg0 = k*PCH;
#pragma unroll
        for (int c = 0; c < PCH; c++) {
            float va = sxp[c*512 + tl0*64 + f];
            float vb = sxp[c*512 + tl1*64 + f];
            u64 pa = pack2(va, va);
            u64 pb = pack2(vb, vb);
            const ulonglong2* wq = (const ulonglong2*)(ws + (cg0+c)*HH);
#pragma unroll
            for (int q = 0; q < 8; q++) {
                ulonglong2 wv = wq[q];
                acc0[2*q]   = fma2(pa, wv.x, acc0[2*q]);
                acc0[2*q+1] = fma2(pa, wv.y, acc0[2*q+1]);
                acc1[2*q]   = fma2(pb, wv.x, acc1[2*q]);
                acc1[2*q+1] = fma2(pb, wv.y, acc1[2*q+1]);
            }
        }
        __syncthreads();                 // all readers done before refill
        int kn = k + PST;
        if (kn < CC/PCH) {
#pragma unroll
            for (int j = 0; j < 4; j++) {
                int q = tid + j*256;
                int c = q >> 7, r = q & 127;
                int tt = r >> 4, f4 = r & 15;
                cp16(smem_u32(&sx[st][q*4]),
                     xbase + (size_t)(kn*PCH + c)*TT*FF + tt*FF + f4*4);
            }
        }
        asm volatile("cp.async.commit_group;");   // keep group accounting aligned
    }

    int t = t0 + tl0;   // thread's first row (second is t+1)
#pragma unroll
    for (int q = 0; q < 16; q++) {
        float a0, a1, c0v, c1v;
        unpack2(acc0[q], a0, a1);
        unpack2(acc1[q], c0v, c1v);
        int h0 = 2*q, h1 = 2*q+1;
        float* o0 = outg + ((size_t)(b*HH+h0)*TT + t)*FF + f;
        float* o1 = outg + ((size_t)(b*HH+h1)*TT + t)*FF + f;
        o0[0]  = a0  + bs[h0];
        o0[FF] = c0v + bs[h0];
        o1[0]  = a1  + bs[h1];
        o1[FF] = c1v + bs[h1];
    }
}

// ============================================================
// K2: banded correlation — exact R11 (K2S=70, LDS.64)
// ============================================================
#define K2T 64
#define K2S 70
__global__ void __launch_bounds__(256) corr_kernel()
{
    __shared__ float sm[K2T*K2S];
    __shared__ float sf[(K2T+31)*K2S];

    int b = blockIdx.z, h = blockIdx.y, t0 = blockIdx.x * K2T;
    int tid = threadIdx.x;   // 256

    const float* xmp = g_xm1 + ((size_t)(b*HH+h)*TT)*FF;
    const float* xfp = g_xf1 + ((size_t)(b*HH+h)*TT)*FF;

    for (int i = tid; i < K2T*FF; i += 256) {
        int r = i >> 6, fc = i & 63;
        sm[r*K2S + fc] = xmp[(size_t)(t0+r)*FF + fc];
    }
    for (int i = tid; i < (K2T+31)*FF; i += 256) {
        int r = i >> 6, fc = i & 63;
        int tt = t0 + r - 31;
        sf[r*K2S + fc] = (tt >= 0) ? xfp[(size_t)tt*FF + fc] : 0.f;
    }
    __syncthreads();

    int tl0 = (tid >> 3) << 1;   // 0,2,...,62
    int d0  = (tid & 7)  << 2;   // 0,4,...,28

    u64 acc[2][4];
#pragma unroll
    for (int i = 0; i < 2; i++)
#pragma unroll
        for (int j = 0; j < 4; j++) acc[i][j] = 0ull;

#pragma unroll 4
    for (int fcp = 0; fcp < FF/2; fcp++) {
        u64 a[2], br[5];
#pragma unroll
        for (int i = 0; i < 2; i++)
            a[i] = *(const u64*)(sm + (tl0+i)*K2S + fcp*2);
#pragma unroll
        for (int k = 0; k < 5; k++)
            br[k] = *(const u64*)(sf + (tl0+d0+k)*K2S + fcp*2);
#pragma unroll
        for (int i = 0; i < 2; i++)
#pragma unroll
            for (int j = 0; j < 4; j++)
                acc[i][j] = fma2(a[i], br[i+j], acc[i][j]);
    }

#pragma unroll
    for (int i = 0; i < 2; i++) {
        float4 v; float x0, x1;
        unpack2(acc[i][0], x0, x1); v.x = x0 + x1;
        unpack2(acc[i][1], x0, x1); v.y = x0 + x1;
        unpack2(acc[i][2], x0, x1); v.z = x0 + x1;
        unpack2(acc[i][3], x0, x1); v.w = x0 + x1;
        *(float4*)(g_corr + (((size_t)(b*HH+h)*TT + (t0+tl0+i))*DD + d0)) = v;
    }
}

// ============================================================
// K3: conv + mask + softmax; scatters weights into 8t-group g_swq — R11
// ============================================================
__global__ void conv_softmax_kernel(const float* __restrict__ wc,
                                    const float* __restrict__ bc)
{
    __shared__ float sc[16][12*36];
    __shared__ float wcs[HH*15];
    int tid = threadIdx.x;  // 256
    int b = blockIdx.y, t0 = blockIdx.x * 8;

    for (int i = tid; i < HH*15; i += 256) wcs[i] = wc[i];

    int d  = tid & 31;
    int tl = tid >> 5;
    float acc = 0.f;

#pragma unroll 1
    for (int ph = 0; ph < 2; ph++) {
        __syncthreads();
        const float* cpb = g_corr + ((size_t)(b*HH + ph*16)*TT)*DD;
        for (int i = tid; i < 16*12*34; i += 256) {
            int h   = i / 408;
            int rem = i - h*408;
            int r   = rem / 34;
            int col = rem - r*34;
            int tt = t0 - 3 + r, dd = col - 1;
            float v = 0.f;
            if (tt >= 0 && tt < TT && dd >= 0 && dd < DD)
                v = cpb[(size_t)h*TT*DD + (size_t)tt*DD + dd];
            sc[h][r*36 + col] = v;
        }
        __syncthreads();
#pragma unroll 1
        for (int h = 0; h < 16; h++) {
            const float* s  = sc[h] + tl*36 + d;
            const float* wv = wcs + (ph*16 + h)*15;
#pragma unroll
            for (int kh = 0; kh < 5; kh++)
#pragma unroll
                for (int kw = 0; kw < 3; kw++)
                    acc = fmaf(s[kh*36 + kw], wv[kh*3 + kw], acc);
        }
    }

    acc += bc[0];
    int t = t0 + tl;
    if (t + d < DD - 1) acc = -1e13f;

    float m = acc;
#pragma unroll
    for (int o = 16; o; o >>= 1) m = fmaxf(m, __shfl_xor_sync(0xffffffffu, m, o));
    float e = expf(acc - m);
    float s = e;
#pragma unroll
    for (int o = 16; o; o >>= 1) s += __shfl_xor_sync(0xffffffffu, s, o);

    float wv = e / s;

    int tile = t >> 6;
    int tg   = (t >> 3) & 7;
    int ii   = t & 7;
    u64* base = g_swq + (size_t)(b*8 + tile)*2496 + tg*312;
    base[(d + ii)*8 + ii] = pack2(wv, wv);
    if (d < 7) {
        int rl = (d < ii) ? d : 32 + d;
        base[rl*8 + ii] = 0ull;
    }
}

// ============================================================
// K4: out[b,c,t,f] = sum_d w[b,t,d] * xf[b,c,t+d-31,f] — R11
// ============================================================
#define K4T 64
__global__ void __launch_bounds__(256) out_kernel(const float* __restrict__ xf,
                                                  float* __restrict__ out)
{
    __shared__ __align__(16) float sx[2][(K4T+31)*FF];  // 48640 B
    __shared__ __align__(16) u64 swq[2496];              // 19968 B

    int b = blockIdx.z, cpair = blockIdx.y, tile = blockIdx.x;
    int t0 = tile * K4T;
    int tid = threadIdx.x;  // 256

    {
        int base4 = (t0 - 31) * (FF/4);
#pragma unroll
        for (int cs = 0; cs < 2; cs++) {
            const float4* xp4 = (const float4*)(xf + ((size_t)(b*CC + cpair*2 + cs)*TT)*FF);
            float4* sx4 = (float4*)sx[cs];
#pragma unroll
            for (int k = 0; k < 6; k++) {
                int i = tid + k*256;
                if (i < (K4T+31)*(FF/4)) {
                    int src = base4 + i;
                    sx4[i] = (src >= 0) ? xp4[src]
                                        : make_float4(0.f, 0.f, 0.f, 0.f);
                }
            }
        }
    }
    {
        const uint4* src = (const uint4*)(g_swq + (size_t)(b*8 + tile)*2496);
        uint4* dst = (uint4*)swq;
#pragma unroll
        for (int k = 0; k < 5; k++) {
            int i = tid + k*256;
            if (i < 1248) dst[i] = src[i];
        }
    }
    __syncthreads();

    int cs = tid >> 7;
    int r  = tid & 127;
    int fq = r & 15;
    int tg = r >> 4;
    int tb = tg << 3;

    u64 acc[8][2];
#pragma unroll
    for (int i = 0; i < 8; i++) { acc[i][0] = 0ull; acc[i][1] = 0ull; }

    const float* xrow = sx[cs] + tb*FF + fq*4;
    const ulonglong2* wq = (const ulonglong2*)(swq + (size_t)tg*312);

#pragma unroll 3
    for (int rl = 0; rl < 39; rl++) {
        ulonglong2 xv = *(const ulonglong2*)(xrow + rl*FF);
        ulonglong2 q0 = wq[rl*4];
        ulonglong2 q1 = wq[rl*4 + 1];
        ulonglong2 q2 = wq[rl*4 + 2];
        ulonglong2 q3 = wq[rl*4 + 3];
        acc[0][0] = fma2(xv.x, q0.x, acc[0][0]);
        acc[0][1] = fma2(xv.y, q0.x, acc[0][1]);
        acc[1][0] = fma2(xv.x, q0.y, acc[1][0]);
        acc[1][1] = fma2(xv.y, q0.y, acc[1][1]);
        acc[2][0] = fma2(xv.x, q1.x, acc[2][0]);
        acc[2][1] = fma2(xv.y, q1.x, acc[2][1]);
        acc[3][0] = fma2(xv.x, q1.y, acc[3][0]);
        acc[3][1] = fma2(xv.y, q1.y, acc[3][1]);
        acc[4][0] = fma2(xv.x, q2.x, acc[4][0]);
        acc[4][1] = fma2(xv.y, q2.x, acc[4][1]);
        acc[5][0] = fma2(xv.x, q2.y, acc[5][0]);
        acc[5][1] = fma2(xv.y, q2.y, acc[5][1]);
        acc[6][0] = fma2(xv.x, q3.x, acc[6][0]);
        acc[6][1] = fma2(xv.y, q3.x, acc[6][1]);
        acc[7][0] = fma2(xv.x, q3.y, acc[7][0]);
        acc[7][1] = fma2(xv.y, q3.y, acc[7][1]);
    }

    float* op = out + ((size_t)(b*CC + cpair*2 + cs)*TT + (t0 + tb))*FF + fq*4;
#pragma unroll
    for (int i = 0; i < 8; i++) {
        float4 v;
        unpack2(acc[i][0], v.x, v.y);
        unpack2(acc[i][1], v.z, v.w);
        *(float4*)(op + (size_t)i*FF) = v;
    }
}

// ============================================================
extern "C" void kernel_launch(void* const* d_in, const int* in_sizes, int n_in,
                              void* d_out, int out_size)
{
    const float* xm = (const float*)d_in[0];
    const float* xf = (const float*)d_in[1];
    const float* w1 = (const float*)d_in[2];
    const float* b1 = (const float*)d_in[3];
    const float* w2 = (const float*)d_in[4];
    const float* b2 = (const float*)d_in[5];
    const float* wc = (const float*)d_in[6];
    const float* bc = (const float*)d_in[7];
    float* out = (float*)d_out;

    (void)in_sizes; (void)n_in; (void)out_size;

    // 3 no-ops so the profiler's fixed capture slot (4th launch) = proj.
    nop_kernel<<<1, 32>>>();
    nop_kernel<<<1, 32>>>();
    nop_kernel<<<1, 32>>>();

    proj_kernel<<<dim3(128, 2), 256>>>(xm, xf, w1, b1, w2, b2);   // #4 <- profiled

    dim3 g2(TT/K2T, HH, BB);
    corr_kernel<<<g2, 256>>>();

    dim3 g3(TT/8, BB);
    conv_softmax_kernel<<<g3, 256>>>(wc, bc);

    dim3 g4(TT/K4T, CC/2, BB);
    out_kernel<<<g4, 256>>>(xf, out);
}